// round 14
// baseline (speedup 1.0000x reference)
#include <cuda_runtime.h>
#include <cuda_bf16.h>
#include <cuda_fp16.h>
#include <cstdint>

// Problem constants (B=4, N=50000, E=800000, C_IN=C_OUT=128)
#define GB 4
#define GC 128
#define MAXN 50000
#define MAXE 800000
#define TILE_M 128
#define APAD 136   // padded bf16 row (272B stride): conflict-free ldmatrix
#define SCAN_TPB 1024
#define MAX_SCAN_BLOCKS 128

// y = x @ W scratch, fp16 (51.2 MB -> fits L2)
__device__ __half g_y[(size_t)GB * MAXN * GC];
// CSR structures (g_cnt: zeroed by scan_fused each run; zero-init for run 1)
__device__ int g_cnt[MAXN];
__device__ int g_rowptr[MAXN + 1];
__device__ int g_cursor[MAXN];
__device__ unsigned long long g_pub[MAX_SCAN_BLOCKS];  // decoupled-lookback slots
__device__ unsigned long long g_csr[MAXE];  // packed (col | val<<32), row-grouped
// Pre-transposed, hi/lo-split W images: [n][k] bf16, padded to APAD
__device__ __align__(16) __nv_bfloat16 g_Whi[GC * APAD];
__device__ __align__(16) __nv_bfloat16 g_Wlo[GC * APAD];

// ---------------------------------------------------------------------------
// PTX helpers (base sm_103 target — no 'a' features)
// ---------------------------------------------------------------------------
__device__ __forceinline__ uint32_t smem_u32(const void* p) {
    uint32_t a;
    asm("{ .reg .u64 t; cvta.to.shared.u64 t, %1; cvt.u32.u64 %0, t; }"
        : "=r"(a) : "l"(p));
    return a;
}
__device__ __forceinline__ void ldsm4(uint32_t* r, uint32_t addr) {
    asm volatile("ldmatrix.sync.aligned.m8n8.x4.shared.b16 {%0,%1,%2,%3}, [%4];"
                 : "=r"(r[0]), "=r"(r[1]), "=r"(r[2]), "=r"(r[3]) : "r"(addr));
}
__device__ __forceinline__ void mma16816(float* d, const uint32_t* a, const uint32_t* b) {
    asm volatile("mma.sync.aligned.m16n8k16.row.col.f32.bf16.bf16.f32 "
                 "{%0,%1,%2,%3}, {%4,%5,%6,%7}, {%8,%9}, {%0,%1,%2,%3};"
                 : "+f"(d[0]), "+f"(d[1]), "+f"(d[2]), "+f"(d[3])
                 : "r"(a[0]), "r"(a[1]), "r"(a[2]), "r"(a[3]),
                   "r"(b[0]), "r"(b[1]));
}

// ---------------------------------------------------------------------------
// W prep: B[n][k] = W[k][n], split into bf16 hi + lo residual.
// ---------------------------------------------------------------------------
__global__ void wprep_kernel(const float* __restrict__ W) {
    int idx = blockIdx.x * blockDim.x + threadIdx.x;
    if (idx >= GC * GC) return;
    int n = idx >> 7, k = idx & 127;
    float v = W[k * GC + n];
    __nv_bfloat16 h = __float2bfloat16(v);
    __nv_bfloat16 l = __float2bfloat16(v - __bfloat162float(h));
    g_Whi[n * APAD + k] = h;
    g_Wlo[n * APAD + k] = l;
}

// ---------------------------------------------------------------------------
// HMMA GEMM over row range [row0, row_end): y = x @ W, 3-pass bf16 split,
// fp16 output. 256 threads, tile 128x128x128. x loads streaming (__ldcs).
// ---------------------------------------------------------------------------
__global__ void __launch_bounds__(256, 1)
gemm_hmma_kernel(const float* __restrict__ x, int row0, int row_end) {
    extern __shared__ __nv_bfloat16 sm[];
    __nv_bfloat16* sAhi = sm;                  // 128 * APAD
    __nv_bfloat16* sAlo = sm + GC * APAD;
    __nv_bfloat16* sBhi = sm + 2 * GC * APAD;
    __nv_bfloat16* sBlo = sm + 3 * GC * APAD;

    int tid = threadIdx.x, wid = tid >> 5, lane = tid & 31;
    int row_base = row0 + blockIdx.x * TILE_M;

    // Copy pre-split W images
    {
        const uint4* sh = (const uint4*)g_Whi;
        const uint4* sl = (const uint4*)g_Wlo;
        uint4* dh = (uint4*)sBhi;
        uint4* dl = (uint4*)sBlo;
        for (int i = tid; i < (GC * APAD * 2) / 16; i += 256) {
            dh[i] = sh[i];
            dl[i] = sl[i];
        }
    }

    // Load A tile (128 x 128 f32) streaming, convert to bf16 hi/lo
    {
        const float4* src = (const float4*)(x + (size_t)row_base * GC);
        #pragma unroll
        for (int j = 0; j < 16; j++) {
            int i = tid + j * 256;
            int row = i >> 5, c4 = i & 31;
            float4 v = make_float4(0.f, 0.f, 0.f, 0.f);
            if (row_base + row < row_end) v = __ldcs(src + i);
            __nv_bfloat16 h0 = __float2bfloat16(v.x), h1 = __float2bfloat16(v.y);
            __nv_bfloat16 h2 = __float2bfloat16(v.z), h3 = __float2bfloat16(v.w);
            __nv_bfloat16 l0 = __float2bfloat16(v.x - __bfloat162float(h0));
            __nv_bfloat16 l1 = __float2bfloat16(v.y - __bfloat162float(h1));
            __nv_bfloat16 l2 = __float2bfloat16(v.z - __bfloat162float(h2));
            __nv_bfloat16 l3 = __float2bfloat16(v.w - __bfloat162float(h3));
            int off = row * APAD + c4 * 4;
            uint32_t hh0 = (uint32_t)__bfloat16_as_ushort(h0) | ((uint32_t)__bfloat16_as_ushort(h1) << 16);
            uint32_t hh1 = (uint32_t)__bfloat16_as_ushort(h2) | ((uint32_t)__bfloat16_as_ushort(h3) << 16);
            uint32_t ll0 = (uint32_t)__bfloat16_as_ushort(l0) | ((uint32_t)__bfloat16_as_ushort(l1) << 16);
            uint32_t ll1 = (uint32_t)__bfloat16_as_ushort(l2) | ((uint32_t)__bfloat16_as_ushort(l3) << 16);
            *(uint2*)(sAhi + off) = make_uint2(hh0, hh1);
            *(uint2*)(sAlo + off) = make_uint2(ll0, ll1);
        }
    }
    __syncthreads();

    int r0 = wid * 16;

    uint32_t aRowOff = ((uint32_t)(r0 + (lane & 15)) * APAD + (uint32_t)(lane >> 4) * 8) * 2;
    uint32_t aHiBase = smem_u32(sAhi) + aRowOff;
    uint32_t aLoBase = smem_u32(sAlo) + aRowOff;
    uint32_t bRowOff = ((uint32_t)((lane & 7) + ((lane >> 4) << 3)) * APAD
                        + (uint32_t)((lane >> 3) & 1) * 8) * 2;
    uint32_t bHi0 = smem_u32(sBhi) + bRowOff;
    uint32_t bLo0 = smem_u32(sBlo) + bRowOff;

    float acc[16][4];
    #pragma unroll
    for (int t = 0; t < 16; t++)
        #pragma unroll
        for (int j = 0; j < 4; j++) acc[t][j] = 0.f;

    #pragma unroll
    for (int ks = 0; ks < 8; ks++) {
        uint32_t ahi[4], alo[4];
        ldsm4(ahi, aHiBase + ks * 32);
        ldsm4(alo, aLoBase + ks * 32);
        #pragma unroll
        for (int nt2 = 0; nt2 < 8; nt2++) {
            uint32_t bhi[4], blo[4];
            uint32_t boff = (uint32_t)(nt2 * 16) * APAD * 2 + ks * 32;
            ldsm4(bhi, bHi0 + boff);
            ldsm4(blo, bLo0 + boff);
            mma16816(acc[nt2 * 2],     ahi, bhi);
            mma16816(acc[nt2 * 2 + 1], ahi, bhi + 2);
            mma16816(acc[nt2 * 2],     alo, bhi);
            mma16816(acc[nt2 * 2 + 1], alo, bhi + 2);
            mma16816(acc[nt2 * 2],     ahi, blo);
            mma16816(acc[nt2 * 2 + 1], ahi, blo + 2);
        }
    }

    // Epilogue: fp16 stores (normal policy — y is re-read by gathers)
    {
        int rlo = r0 + (lane >> 2);
        int col = (lane & 3) * 2;
        long g0 = (long)row_base + rlo;
        long g1 = g0 + 8;
        __half* y0 = g_y + (size_t)g0 * GC + col;
        __half* y1 = g_y + (size_t)g1 * GC + col;
        bool ok0 = g0 < row_end, ok1 = g1 < row_end;
        #pragma unroll
        for (int nt = 0; nt < 16; nt++) {
            if (ok0) *(__half2*)(y0 + nt * 8) =
                __floats2half2_rn(acc[nt][0], acc[nt][1]);
            if (ok1) *(__half2*)(y1 + nt * 8) =
                __floats2half2_rn(acc[nt][2], acc[nt][3]);
        }
    }
}

// ---------------------------------------------------------------------------
// CSR build (side stream): hist -> fused scan (decoupled lookback) -> fill
// g_cnt arrives zeroed (previous run's scan zeroed it; static init run 1).
// ---------------------------------------------------------------------------
__global__ void hist_kernel(const int* __restrict__ erow, int E) {
    int e = blockIdx.x * blockDim.x + threadIdx.x;
    if (e < E) atomicAdd(&g_cnt[erow[e]], 1);
}

// One launch: block-local scan + publish block sum (value|flag in one 64-bit
// word) + lookback over predecessors + global write of rowptr/cursor.
// Also zeroes g_cnt for the next replay. g_pub is reset by fill_kernel.
__global__ void scan_fused_kernel(int N) {
    __shared__ int wsum[32];
    __shared__ int s_prefix;
    int t = threadIdx.x, lane = t & 31, w = t >> 5;
    int bid = blockIdx.x;
    int i = bid * SCAN_TPB + t;
    int v = (i < N) ? g_cnt[i] : 0;

    // Block-wide inclusive scan
    int s = v;
    #pragma unroll
    for (int off = 1; off < 32; off <<= 1) {
        int u = __shfl_up_sync(0xffffffffu, s, off);
        if (lane >= off) s += u;
    }
    if (lane == 31) wsum[w] = s;
    __syncthreads();
    if (w == 0) {
        int ws = wsum[lane];
        #pragma unroll
        for (int off = 1; off < 32; off <<= 1) {
            int u = __shfl_up_sync(0xffffffffu, ws, off);
            if (lane >= off) ws += u;
        }
        wsum[lane] = ws;
    }
    __syncthreads();
    int incl = s + (w ? wsum[w - 1] : 0);
    int blocktotal = wsum[31];

    // Publish own sum, then look back over predecessors (aggregates only;
    // all <=49 blocks are resident, so forward progress is guaranteed).
    if (t == 0) {
        atomicExch(&g_pub[bid],
                   (unsigned long long)(unsigned)blocktotal | (1ull << 63));
        int pre = 0;
        for (int j = 0; j < bid; j++) {
            unsigned long long p;
            do { p = atomicAdd(&g_pub[j], 0ull); } while (!(p >> 63));
            pre += (int)(unsigned)p;
        }
        s_prefix = pre;
    }
    __syncthreads();

    int incl_global = s_prefix + incl;
    if (i < N) {
        g_rowptr[i + 1] = incl_global;
        g_cursor[i] = incl_global - v;
        g_cnt[i] = 0;                 // ready for next replay
    }
    if (i == 0) g_rowptr[0] = 0;
}

__global__ void fill_kernel(const int* __restrict__ erow,
                            const int* __restrict__ ecol,
                            const float* __restrict__ evals,
                            int E) {
    // Reset lookback slots for the next replay (runs strictly after scan).
    if (blockIdx.x == 0 && threadIdx.x < MAX_SCAN_BLOCKS)
        g_pub[threadIdx.x] = 0ull;

    int e = blockIdx.x * blockDim.x + threadIdx.x;
    if (e < E) {
        int r = erow[e];
        int pos = atomicAdd(&g_cursor[r], 1);
        unsigned long long m = (unsigned long long)(unsigned)ecol[e]
                             | ((unsigned long long)__float_as_uint(evals[e]) << 32);
        g_csr[pos] = m;
    }
}

// ---------------------------------------------------------------------------
// Per-batch gather: out[b,r,:] = relu(sum val*y16[b,col,:] + bias)
// One warp per node row; 4-edge unroll; fp16 y, fp32 accumulate.
// out stores streaming (__stcs).
// ---------------------------------------------------------------------------
__device__ __forceinline__ void acc_half8(float4& a, float v, uint2 u) {
    float2 f0 = __half22float2(*(__half2*)&u.x);
    float2 f1 = __half22float2(*(__half2*)&u.y);
    a.x += v * f0.x; a.y += v * f0.y;
    a.z += v * f1.x; a.w += v * f1.y;
}

__global__ void gather_b_kernel(const float* __restrict__ bias,
                                float* __restrict__ out,
                                int N, int b) {
    int r = (blockIdx.x * blockDim.x + threadIdx.x) >> 5;
    int lane = threadIdx.x & 31;
    if (r >= N) return;

    float4 bv = ((const float4*)bias)[lane];
    int e   = g_rowptr[r];
    int end = g_rowptr[r + 1];

    const __half* yb = g_y + (size_t)b * N * GC;

    float4 a0 = make_float4(0.f, 0.f, 0.f, 0.f);
    float4 a1 = a0;

    for (; e + 4 <= end; e += 4) {
        unsigned long long m0 = g_csr[e];
        unsigned long long m1 = g_csr[e + 1];
        unsigned long long m2 = g_csr[e + 2];
        unsigned long long m3 = g_csr[e + 3];
        int   c0 = (int)(m0 & 0xffffffffu); float v0 = __uint_as_float((unsigned)(m0 >> 32));
        int   c1 = (int)(m1 & 0xffffffffu); float v1 = __uint_as_float((unsigned)(m1 >> 32));
        int   c2 = (int)(m2 & 0xffffffffu); float v2 = __uint_as_float((unsigned)(m2 >> 32));
        int   c3 = (int)(m3 & 0xffffffffu); float v3 = __uint_as_float((unsigned)(m3 >> 32));
        uint2 u0 = ((const uint2*)(yb + (size_t)c0 * GC))[lane];
        uint2 u1 = ((const uint2*)(yb + (size_t)c1 * GC))[lane];
        uint2 u2 = ((const uint2*)(yb + (size_t)c2 * GC))[lane];
        uint2 u3 = ((const uint2*)(yb + (size_t)c3 * GC))[lane];
        acc_half8(a0, v0, u0);
        acc_half8(a1, v1, u1);
        acc_half8(a0, v2, u2);
        acc_half8(a1, v3, u3);
    }
    for (; e < end; e++) {
        unsigned long long m = g_csr[e];
        int   c = (int)(m & 0xffffffffu);
        float v = __uint_as_float((unsigned)(m >> 32));
        uint2 u = ((const uint2*)(yb + (size_t)c * GC))[lane];
        acc_half8(a0, v, u);
    }

    float4 o;
    o.x = fmaxf(a0.x + a1.x + bv.x, 0.f);
    o.y = fmaxf(a0.y + a1.y + bv.y, 0.f);
    o.z = fmaxf(a0.z + a1.z + bv.z, 0.f);
    o.w = fmaxf(a0.w + a1.w + bv.w, 0.f);
    __stcs((float4*)(out + ((size_t)b * N + r) * GC) + lane, o);
}

// ---------------------------------------------------------------------------
// Launch. CSR (3 launches, no memset) on side stream 1; per-batch GEMMs on
// main stream; gathers on two concurrent streams, pipelined behind GEMMs.
// Inputs: x [B,N,C], edge_row [E], edge_col [E], edge_vals [E], W [C,C], b [C]
// ---------------------------------------------------------------------------
extern "C" void kernel_launch(void* const* d_in, const int* in_sizes, int n_in,
                              void* d_out, int out_size) {
    const float* x     = (const float*)d_in[0];
    const int*   erow  = (const int*)d_in[1];
    const int*   ecol  = (const int*)d_in[2];
    const float* evals = (const float*)d_in[3];
    const float* W     = (const float*)d_in[4];
    const float* bias  = (const float*)d_in[5];
    float* out = (float*)d_out;

    int E = in_sizes[1];
    int N = in_sizes[0] / (GB * GC);

    const size_t smem_bytes = (size_t)4 * GC * APAD * sizeof(__nv_bfloat16); // 139264

    static cudaStream_t s_csr = nullptr, s_gat = nullptr, s_gat2 = nullptr;
    static cudaEvent_t ev_fork = nullptr, ev_csr = nullptr;
    static cudaEvent_t ev_done = nullptr, ev_done2 = nullptr;
    static cudaEvent_t ev_gemm[GB] = {};
    if (s_csr == nullptr) {
        cudaStreamCreateWithFlags(&s_csr, cudaStreamNonBlocking);
        cudaStreamCreateWithFlags(&s_gat, cudaStreamNonBlocking);
        cudaStreamCreateWithFlags(&s_gat2, cudaStreamNonBlocking);
        cudaEventCreateWithFlags(&ev_fork, cudaEventDisableTiming);
        cudaEventCreateWithFlags(&ev_csr, cudaEventDisableTiming);
        cudaEventCreateWithFlags(&ev_done, cudaEventDisableTiming);
        cudaEventCreateWithFlags(&ev_done2, cudaEventDisableTiming);
        for (int b = 0; b < GB; b++)
            cudaEventCreateWithFlags(&ev_gemm[b], cudaEventDisableTiming);
        cudaFuncSetAttribute(gemm_hmma_kernel,
                             cudaFuncAttributeMaxDynamicSharedMemorySize,
                             (int)smem_bytes);
    }

    int nblk = (N + SCAN_TPB - 1) / SCAN_TPB;   // 49 for N=50000

    // --- fork: CSR build on side stream (no memset; g_cnt pre-zeroed) ---
    cudaEventRecord(ev_fork, 0);
    cudaStreamWaitEvent(s_csr, ev_fork, 0);
    hist_kernel<<<(E + 255) / 256, 256, 0, s_csr>>>(erow, E);
    scan_fused_kernel<<<nblk, SCAN_TPB, 0, s_csr>>>(N);
    fill_kernel<<<(E + 255) / 256, 256, 0, s_csr>>>(erow, ecol, evals, E);
    cudaEventRecord(ev_csr, s_csr);

    // --- main stream: W prep, then per-batch GEMM ---
    wprep_kernel<<<(GC * GC + 255) / 256, 256>>>(W);
    int ntb = (N + TILE_M - 1) / TILE_M;   // tiles per batch
    for (int b = 0; b < GB; b++) {
        gemm_hmma_kernel<<<ntb, 256, smem_bytes>>>(x, b * N, (b + 1) * N);
        cudaEventRecord(ev_gemm[b], 0);
    }

    // --- two gather streams: pairs run concurrently ---
    int gblocks = (N + 7) / 8;   // 8 warps/block, 1 warp per row

    cudaStreamWaitEvent(s_gat, ev_csr, 0);
    cudaStreamWaitEvent(s_gat, ev_gemm[0], 0);
    gather_b_kernel<<<gblocks, 256, 0, s_gat>>>(bias, out, N, 0);
    cudaStreamWaitEvent(s_gat, ev_gemm[1], 0);
    gather_b_kernel<<<gblocks, 256, 0, s_gat>>>(bias, out, N, 1);
    cudaEventRecord(ev_done, s_gat);

    cudaStreamWaitEvent(s_gat2, ev_csr, 0);
    cudaStreamWaitEvent(s_gat2, ev_gemm[2], 0);
    gather_b_kernel<<<gblocks, 256, 0, s_gat2>>>(bias, out, N, 2);
    cudaStreamWaitEvent(s_gat2, ev_gemm[3], 0);
    gather_b_kernel<<<gblocks, 256, 0, s_gat2>>>(bias, out, N, 3);
    cudaEventRecord(ev_done2, s_gat2);

    cudaStreamWaitEvent(0, ev_done, 0);
    cudaStreamWaitEvent(0, ev_done2, 0);
}

// round 15
// speedup vs baseline: 1.0740x; 1.0740x over previous
#include <cuda_runtime.h>
#include <cuda_bf16.h>
#include <cuda_fp16.h>
#include <cstdint>

// Problem constants (B=4, N=50000, E=800000, C_IN=C_OUT=128)
#define GB 4
#define GC 128
#define MAXN 50000
#define MAXE 800000
#define TILE_M 128
#define APAD 136   // padded bf16 row (272B stride): conflict-free ldmatrix
#define SCAN_TPB 1024
#define MAX_SCAN_BLOCKS 128

// y = x @ W scratch, fp16 (51.2 MB -> fits L2)
__device__ __half g_y[(size_t)GB * MAXN * GC];
// CSR structures
__device__ int g_cnt[MAXN];
__device__ int g_rowptr[MAXN + 1];
__device__ int g_cursor[MAXN];
__device__ int g_bsum[MAX_SCAN_BLOCKS];
__device__ int g_boff[MAX_SCAN_BLOCKS];
__device__ unsigned g_csr[MAXE];   // packed (val_fp16 << 16) | col_u16, row-grouped
// Pre-transposed, hi/lo-split W images: [n][k] bf16, padded to APAD
__device__ __align__(16) __nv_bfloat16 g_Whi[GC * APAD];
__device__ __align__(16) __nv_bfloat16 g_Wlo[GC * APAD];

// ---------------------------------------------------------------------------
// PTX helpers (base sm_103 target — no 'a' features)
// ---------------------------------------------------------------------------
__device__ __forceinline__ uint32_t smem_u32(const void* p) {
    uint32_t a;
    asm("{ .reg .u64 t; cvta.to.shared.u64 t, %1; cvt.u32.u64 %0, t; }"
        : "=r"(a) : "l"(p));
    return a;
}
__device__ __forceinline__ void ldsm4(uint32_t* r, uint32_t addr) {
    asm volatile("ldmatrix.sync.aligned.m8n8.x4.shared.b16 {%0,%1,%2,%3}, [%4];"
                 : "=r"(r[0]), "=r"(r[1]), "=r"(r[2]), "=r"(r[3]) : "r"(addr));
}
__device__ __forceinline__ void mma16816(float* d, const uint32_t* a, const uint32_t* b) {
    asm volatile("mma.sync.aligned.m16n8k16.row.col.f32.bf16.bf16.f32 "
                 "{%0,%1,%2,%3}, {%4,%5,%6,%7}, {%8,%9}, {%0,%1,%2,%3};"
                 : "+f"(d[0]), "+f"(d[1]), "+f"(d[2]), "+f"(d[3])
                 : "r"(a[0]), "r"(a[1]), "r"(a[2]), "r"(a[3]),
                   "r"(b[0]), "r"(b[1]));
}

// ---------------------------------------------------------------------------
// W prep: B[n][k] = W[k][n], split into bf16 hi + lo residual.
// ---------------------------------------------------------------------------
__global__ void wprep_kernel(const float* __restrict__ W) {
    int idx = blockIdx.x * blockDim.x + threadIdx.x;
    if (idx >= GC * GC) return;
    int n = idx >> 7, k = idx & 127;
    float v = W[k * GC + n];
    __nv_bfloat16 h = __float2bfloat16(v);
    __nv_bfloat16 l = __float2bfloat16(v - __bfloat162float(h));
    g_Whi[n * APAD + k] = h;
    g_Wlo[n * APAD + k] = l;
}

// ---------------------------------------------------------------------------
// HMMA GEMM over row range [row0, row_end): y = x @ W, 3-pass bf16 split,
// fp16 output. 256 threads, tile 128x128x128. x loads streaming (__ldcs).
// ---------------------------------------------------------------------------
__global__ void __launch_bounds__(256, 1)
gemm_hmma_kernel(const float* __restrict__ x, int row0, int row_end) {
    extern __shared__ __nv_bfloat16 sm[];
    __nv_bfloat16* sAhi = sm;                  // 128 * APAD
    __nv_bfloat16* sAlo = sm + GC * APAD;
    __nv_bfloat16* sBhi = sm + 2 * GC * APAD;
    __nv_bfloat16* sBlo = sm + 3 * GC * APAD;

    int tid = threadIdx.x, wid = tid >> 5, lane = tid & 31;
    int row_base = row0 + blockIdx.x * TILE_M;

    // Copy pre-split W images
    {
        const uint4* sh = (const uint4*)g_Whi;
        const uint4* sl = (const uint4*)g_Wlo;
        uint4* dh = (uint4*)sBhi;
        uint4* dl = (uint4*)sBlo;
        for (int i = tid; i < (GC * APAD * 2) / 16; i += 256) {
            dh[i] = sh[i];
            dl[i] = sl[i];
        }
    }

    // Load A tile (128 x 128 f32) streaming, convert to bf16 hi/lo
    {
        const float4* src = (const float4*)(x + (size_t)row_base * GC);
        #pragma unroll
        for (int j = 0; j < 16; j++) {
            int i = tid + j * 256;
            int row = i >> 5, c4 = i & 31;
            float4 v = make_float4(0.f, 0.f, 0.f, 0.f);
            if (row_base + row < row_end) v = __ldcs(src + i);
            __nv_bfloat16 h0 = __float2bfloat16(v.x), h1 = __float2bfloat16(v.y);
            __nv_bfloat16 h2 = __float2bfloat16(v.z), h3 = __float2bfloat16(v.w);
            __nv_bfloat16 l0 = __float2bfloat16(v.x - __bfloat162float(h0));
            __nv_bfloat16 l1 = __float2bfloat16(v.y - __bfloat162float(h1));
            __nv_bfloat16 l2 = __float2bfloat16(v.z - __bfloat162float(h2));
            __nv_bfloat16 l3 = __float2bfloat16(v.w - __bfloat162float(h3));
            int off = row * APAD + c4 * 4;
            uint32_t hh0 = (uint32_t)__bfloat16_as_ushort(h0) | ((uint32_t)__bfloat16_as_ushort(h1) << 16);
            uint32_t hh1 = (uint32_t)__bfloat16_as_ushort(h2) | ((uint32_t)__bfloat16_as_ushort(h3) << 16);
            uint32_t ll0 = (uint32_t)__bfloat16_as_ushort(l0) | ((uint32_t)__bfloat16_as_ushort(l1) << 16);
            uint32_t ll1 = (uint32_t)__bfloat16_as_ushort(l2) | ((uint32_t)__bfloat16_as_ushort(l3) << 16);
            *(uint2*)(sAhi + off) = make_uint2(hh0, hh1);
            *(uint2*)(sAlo + off) = make_uint2(ll0, ll1);
        }
    }
    __syncthreads();

    int r0 = wid * 16;

    uint32_t aRowOff = ((uint32_t)(r0 + (lane & 15)) * APAD + (uint32_t)(lane >> 4) * 8) * 2;
    uint32_t aHiBase = smem_u32(sAhi) + aRowOff;
    uint32_t aLoBase = smem_u32(sAlo) + aRowOff;
    uint32_t bRowOff = ((uint32_t)((lane & 7) + ((lane >> 4) << 3)) * APAD
                        + (uint32_t)((lane >> 3) & 1) * 8) * 2;
    uint32_t bHi0 = smem_u32(sBhi) + bRowOff;
    uint32_t bLo0 = smem_u32(sBlo) + bRowOff;

    float acc[16][4];
    #pragma unroll
    for (int t = 0; t < 16; t++)
        #pragma unroll
        for (int j = 0; j < 4; j++) acc[t][j] = 0.f;

    #pragma unroll
    for (int ks = 0; ks < 8; ks++) {
        uint32_t ahi[4], alo[4];
        ldsm4(ahi, aHiBase + ks * 32);
        ldsm4(alo, aLoBase + ks * 32);
        #pragma unroll
        for (int nt2 = 0; nt2 < 8; nt2++) {
            uint32_t bhi[4], blo[4];
            uint32_t boff = (uint32_t)(nt2 * 16) * APAD * 2 + ks * 32;
            ldsm4(bhi, bHi0 + boff);
            ldsm4(blo, bLo0 + boff);
            mma16816(acc[nt2 * 2],     ahi, bhi);
            mma16816(acc[nt2 * 2 + 1], ahi, bhi + 2);
            mma16816(acc[nt2 * 2],     alo, bhi);
            mma16816(acc[nt2 * 2 + 1], alo, bhi + 2);
            mma16816(acc[nt2 * 2],     ahi, blo);
            mma16816(acc[nt2 * 2 + 1], ahi, blo + 2);
        }
    }

    // Epilogue: fp16 stores (normal policy — y is re-read by gathers)
    {
        int rlo = r0 + (lane >> 2);
        int col = (lane & 3) * 2;
        long g0 = (long)row_base + rlo;
        long g1 = g0 + 8;
        __half* y0 = g_y + (size_t)g0 * GC + col;
        __half* y1 = g_y + (size_t)g1 * GC + col;
        bool ok0 = g0 < row_end, ok1 = g1 < row_end;
        #pragma unroll
        for (int nt = 0; nt < 16; nt++) {
            if (ok0) *(__half2*)(y0 + nt * 8) =
                __floats2half2_rn(acc[nt][0], acc[nt][1]);
            if (ok1) *(__half2*)(y1 + nt * 8) =
                __floats2half2_rn(acc[nt][2], acc[nt][3]);
        }
    }
}

// ---------------------------------------------------------------------------
// CSR build (side stream): hist (vectorized) -> 2-level scan -> fill (4B pack)
// ---------------------------------------------------------------------------
__global__ void hist_kernel(const int* __restrict__ erow, int E) {
    int i = blockIdx.x * blockDim.x + threadIdx.x;
    int e = i * 4;
    if (e + 4 <= E) {
        int4 r4 = *(const int4*)(erow + e);
        atomicAdd(&g_cnt[r4.x], 1);
        atomicAdd(&g_cnt[r4.y], 1);
        atomicAdd(&g_cnt[r4.z], 1);
        atomicAdd(&g_cnt[r4.w], 1);
    } else {
        for (; e < E; e++) atomicAdd(&g_cnt[erow[e]], 1);
    }
}

__global__ void scan_block_kernel(int N) {
    __shared__ int wsum[32];
    int t = threadIdx.x, lane = t & 31, w = t >> 5;
    int i = blockIdx.x * SCAN_TPB + t;
    int v = (i < N) ? g_cnt[i] : 0;
    int s = v;
    #pragma unroll
    for (int off = 1; off < 32; off <<= 1) {
        int u = __shfl_up_sync(0xffffffffu, s, off);
        if (lane >= off) s += u;
    }
    if (lane == 31) wsum[w] = s;
    __syncthreads();
    if (w == 0) {
        int ws = wsum[lane];
        #pragma unroll
        for (int off = 1; off < 32; off <<= 1) {
            int u = __shfl_up_sync(0xffffffffu, ws, off);
            if (lane >= off) ws += u;
        }
        wsum[lane] = ws;
    }
    __syncthreads();
    int incl = s + (w ? wsum[w - 1] : 0);
    if (i < N) g_rowptr[i + 1] = incl;     // block-local inclusive
    if (t == SCAN_TPB - 1) g_bsum[blockIdx.x] = incl;
}

__global__ void scan_sums_kernel(int nblk) {
    __shared__ int s[MAX_SCAN_BLOCKS];
    int t = threadIdx.x;
    int v = (t < nblk) ? g_bsum[t] : 0;
    s[t] = v;
    __syncthreads();
    #pragma unroll
    for (int off = 1; off < MAX_SCAN_BLOCKS; off <<= 1) {
        int u = (t >= off) ? s[t - off] : 0;
        __syncthreads();
        s[t] += u;
        __syncthreads();
    }
    if (t < nblk) g_boff[t] = s[t] - v;    // exclusive prefix
}

__global__ void scan_add_kernel(int N) {
    int i = blockIdx.x * SCAN_TPB + threadIdx.x;
    if (i == 0) g_rowptr[0] = 0;
    if (i < N) {
        int rp = g_rowptr[i + 1] + g_boff[blockIdx.x];
        g_rowptr[i + 1] = rp;
        g_cursor[i] = rp - g_cnt[i];
    }
}

__global__ void fill_kernel(const int* __restrict__ erow,
                            const int* __restrict__ ecol,
                            const float* __restrict__ evals,
                            int E) {
    int e = blockIdx.x * blockDim.x + threadIdx.x;
    if (e < E) {
        int r = erow[e];
        int pos = atomicAdd(&g_cursor[r], 1);
        unsigned short vh = __half_as_ushort(__float2half_rn(evals[e]));
        g_csr[pos] = (unsigned)ecol[e] | ((unsigned)vh << 16);
    }
}

// ---------------------------------------------------------------------------
// Per-batch gather: out[b,r,:] = relu(sum val*y16[b,col,:] + bias)
// One warp per node row; 4-edge unroll; 4B packed metadata (u16 col, fp16 val);
// fp16 y, fp32 accumulate; out stores streaming (__stcs).
// ---------------------------------------------------------------------------
__device__ __forceinline__ void acc_half8(float4& a, float v, uint2 u) {
    float2 f0 = __half22float2(*(__half2*)&u.x);
    float2 f1 = __half22float2(*(__half2*)&u.y);
    a.x += v * f0.x; a.y += v * f0.y;
    a.z += v * f1.x; a.w += v * f1.y;
}

__global__ void gather_b_kernel(const float* __restrict__ bias,
                                float* __restrict__ out,
                                int N, int b) {
    int r = (blockIdx.x * blockDim.x + threadIdx.x) >> 5;
    int lane = threadIdx.x & 31;
    if (r >= N) return;

    float4 bv = ((const float4*)bias)[lane];
    int e   = g_rowptr[r];
    int end = g_rowptr[r + 1];

    const __half* yb = g_y + (size_t)b * N * GC;

    float4 a0 = make_float4(0.f, 0.f, 0.f, 0.f);
    float4 a1 = a0;

    for (; e + 4 <= end; e += 4) {
        unsigned m0 = g_csr[e];
        unsigned m1 = g_csr[e + 1];
        unsigned m2 = g_csr[e + 2];
        unsigned m3 = g_csr[e + 3];
        int   c0 = (int)(m0 & 0xffffu); float v0 = __half2float(__ushort_as_half((unsigned short)(m0 >> 16)));
        int   c1 = (int)(m1 & 0xffffu); float v1 = __half2float(__ushort_as_half((unsigned short)(m1 >> 16)));
        int   c2 = (int)(m2 & 0xffffu); float v2 = __half2float(__ushort_as_half((unsigned short)(m2 >> 16)));
        int   c3 = (int)(m3 & 0xffffu); float v3 = __half2float(__ushort_as_half((unsigned short)(m3 >> 16)));
        uint2 u0 = ((const uint2*)(yb + (size_t)c0 * GC))[lane];
        uint2 u1 = ((const uint2*)(yb + (size_t)c1 * GC))[lane];
        uint2 u2 = ((const uint2*)(yb + (size_t)c2 * GC))[lane];
        uint2 u3 = ((const uint2*)(yb + (size_t)c3 * GC))[lane];
        acc_half8(a0, v0, u0);
        acc_half8(a1, v1, u1);
        acc_half8(a0, v2, u2);
        acc_half8(a1, v3, u3);
    }
    for (; e < end; e++) {
        unsigned m = g_csr[e];
        int   c = (int)(m & 0xffffu);
        float v = __half2float(__ushort_as_half((unsigned short)(m >> 16)));
        uint2 u = ((const uint2*)(yb + (size_t)c * GC))[lane];
        acc_half8(a0, v, u);
    }

    float4 o;
    o.x = fmaxf(a0.x + a1.x + bv.x, 0.f);
    o.y = fmaxf(a0.y + a1.y + bv.y, 0.f);
    o.z = fmaxf(a0.z + a1.z + bv.z, 0.f);
    o.w = fmaxf(a0.w + a1.w + bv.w, 0.f);
    __stcs((float4*)(out + ((size_t)b * N + r) * GC) + lane, o);
}

// ---------------------------------------------------------------------------
// Launch. CSR on side stream 1; per-batch GEMMs on main stream; gathers on
// two concurrent streams, pipelined behind GEMMs.
// Inputs: x [B,N,C], edge_row [E], edge_col [E], edge_vals [E], W [C,C], b [C]
// ---------------------------------------------------------------------------
extern "C" void kernel_launch(void* const* d_in, const int* in_sizes, int n_in,
                              void* d_out, int out_size) {
    const float* x     = (const float*)d_in[0];
    const int*   erow  = (const int*)d_in[1];
    const int*   ecol  = (const int*)d_in[2];
    const float* evals = (const float*)d_in[3];
    const float* W     = (const float*)d_in[4];
    const float* bias  = (const float*)d_in[5];
    float* out = (float*)d_out;

    int E = in_sizes[1];
    int N = in_sizes[0] / (GB * GC);

    const size_t smem_bytes = (size_t)4 * GC * APAD * sizeof(__nv_bfloat16); // 139264

    static cudaStream_t s_csr = nullptr, s_gat = nullptr, s_gat2 = nullptr;
    static cudaEvent_t ev_fork = nullptr, ev_csr = nullptr;
    static cudaEvent_t ev_done = nullptr, ev_done2 = nullptr;
    static cudaEvent_t ev_gemm[GB] = {};
    if (s_csr == nullptr) {
        cudaStreamCreateWithFlags(&s_csr, cudaStreamNonBlocking);
        cudaStreamCreateWithFlags(&s_gat, cudaStreamNonBlocking);
        cudaStreamCreateWithFlags(&s_gat2, cudaStreamNonBlocking);
        cudaEventCreateWithFlags(&ev_fork, cudaEventDisableTiming);
        cudaEventCreateWithFlags(&ev_csr, cudaEventDisableTiming);
        cudaEventCreateWithFlags(&ev_done, cudaEventDisableTiming);
        cudaEventCreateWithFlags(&ev_done2, cudaEventDisableTiming);
        for (int b = 0; b < GB; b++)
            cudaEventCreateWithFlags(&ev_gemm[b], cudaEventDisableTiming);
        cudaFuncSetAttribute(gemm_hmma_kernel,
                             cudaFuncAttributeMaxDynamicSharedMemorySize,
                             (int)smem_bytes);
    }

    void* cnt_ptr = nullptr;
    cudaGetSymbolAddress(&cnt_ptr, g_cnt);

    int nblk = (N + SCAN_TPB - 1) / SCAN_TPB;   // 49 for N=50000

    // --- fork: CSR build on side stream ---
    cudaEventRecord(ev_fork, 0);
    cudaStreamWaitEvent(s_csr, ev_fork, 0);
    cudaMemsetAsync(cnt_ptr, 0, (size_t)N * sizeof(int), s_csr);
    hist_kernel<<<(E / 4 + 255) / 256, 256, 0, s_csr>>>(erow, E);
    scan_block_kernel<<<nblk, SCAN_TPB, 0, s_csr>>>(N);
    scan_sums_kernel<<<1, MAX_SCAN_BLOCKS, 0, s_csr>>>(nblk);
    scan_add_kernel<<<nblk, SCAN_TPB, 0, s_csr>>>(N);
    fill_kernel<<<(E + 255) / 256, 256, 0, s_csr>>>(erow, ecol, evals, E);
    cudaEventRecord(ev_csr, s_csr);

    // --- main stream: W prep, then per-batch GEMM ---
    wprep_kernel<<<(GC * GC + 255) / 256, 256>>>(W);
    int ntb = (N + TILE_M - 1) / TILE_M;   // tiles per batch
    for (int b = 0; b < GB; b++) {
        gemm_hmma_kernel<<<ntb, 256, smem_bytes>>>(x, b * N, (b + 1) * N);
        cudaEventRecord(ev_gemm[b], 0);
    }

    // --- two gather streams: pairs run concurrently ---
    int gblocks = (N + 7) / 8;   // 8 warps/block, 1 warp per row

    cudaStreamWaitEvent(s_gat, ev_csr, 0);
    cudaStreamWaitEvent(s_gat, ev_gemm[0], 0);
    gather_b_kernel<<<gblocks, 256, 0, s_gat>>>(bias, out, N, 0);
    cudaStreamWaitEvent(s_gat, ev_gemm[1], 0);
    gather_b_kernel<<<gblocks, 256, 0, s_gat>>>(bias, out, N, 1);
    cudaEventRecord(ev_done, s_gat);

    cudaStreamWaitEvent(s_gat2, ev_csr, 0);
    cudaStreamWaitEvent(s_gat2, ev_gemm[2], 0);
    gather_b_kernel<<<gblocks, 256, 0, s_gat2>>>(bias, out, N, 2);
    cudaStreamWaitEvent(s_gat2, ev_gemm[3], 0);
    gather_b_kernel<<<gblocks, 256, 0, s_gat2>>>(bias, out, N, 3);
    cudaEventRecord(ev_done2, s_gat2);

    cudaStreamWaitEvent(0, ev_done, 0);
    cudaStreamWaitEvent(0, ev_done2, 0);
}